// round 16
// baseline (speedup 1.0000x reference)
#include <cuda_runtime.h>
#include <cuda_fp16.h>
#include <math.h>
#include <stdint.h>

#define N_TOKENS 16384
#define HIDDEN   1024
#define FFN      4096
#define NEXP     8
#define NSLOTS   (N_TOKENS * 2)
#define NSLOTS_PAD (NSLOTS + NEXP * 128)   // 33792
#define MAXTILES 272
#define NCVT_BLOCKS 4096
#define NW1 (32 * MAXTILES)                 // 8704 GEMM1 tile bids
#define NWALL (NW1 + 8 * MAXTILES)          // + 2176 GEMM2 tile bids

// ---------------- scratch (device globals) -----------------------------------------
__device__ __half g_W1h[(size_t)NEXP * HIDDEN * FFN];   // [e][K][N] fp16
__device__ __half g_W2h[(size_t)NEXP * FFN * HIDDEN];
__device__ __half g_xc[(size_t)N_TOKENS * HIDDEN];      // x as fp16 (per token)
__device__ __half g_hh[(size_t)NSLOTS_PAD * FFN];       // h fp16
__device__ int   g_tok[NSLOTS_PAD];                     // slot -> token (pad: 0)
__device__ float g_slot_w[NSLOTS_PAD];                  // slot -> combine weight (pad: 0)
__device__ int   g_token_e[NSLOTS];
__device__ float g_token_w[NSLOTS];
__device__ int   g_count[NEXP], g_cursor[NEXP], g_off_pad[NEXP];
__device__ int   g_tile_e[MAXTILES], g_tile_base[MAXTILES];
__device__ int   g_ntiles, g_npad;
__device__ int   g_done[MAXTILES];                      // per-mtile GEMM1 completion count

// ---------------- helpers ----------------------------------------------------------
__device__ __forceinline__ uint32_t smem_u32(const void* p) {
    uint32_t a;
    asm("{ .reg .u64 t; cvta.to.shared.u64 t, %1; cvt.u32.u64 %0, t; }" : "=r"(a) : "l"(p));
    return a;
}
__device__ __forceinline__ void cpa16(uint32_t d, const void* s) {
    asm volatile("cp.async.cg.shared.global [%0], [%1], 16;" :: "r"(d), "l"(s));
}
__device__ __forceinline__ void ldm_x4(uint32_t* r, uint32_t a) {
    asm volatile("ldmatrix.sync.aligned.m8n8.x4.shared.b16 {%0,%1,%2,%3}, [%4];"
                 : "=r"(r[0]), "=r"(r[1]), "=r"(r[2]), "=r"(r[3]) : "r"(a));
}
__device__ __forceinline__ void ldm_x4t(uint32_t* r, uint32_t a) {
    asm volatile("ldmatrix.sync.aligned.m8n8.x4.trans.shared.b16 {%0,%1,%2,%3}, [%4];"
                 : "=r"(r[0]), "=r"(r[1]), "=r"(r[2]), "=r"(r[3]) : "r"(a));
}
__device__ __forceinline__ void mma_f16(float* d, const uint32_t* a, uint32_t b0, uint32_t b1) {
    asm volatile(
        "mma.sync.aligned.m16n8k16.row.col.f32.f16.f16.f32 "
        "{%0,%1,%2,%3}, {%4,%5,%6,%7}, {%8,%9}, {%0,%1,%2,%3};"
        : "+f"(d[0]), "+f"(d[1]), "+f"(d[2]), "+f"(d[3])
        : "r"(a[0]), "r"(a[1]), "r"(a[2]), "r"(a[3]), "r"(b0), "r"(b1));
}

// ---------------- fused gating + x fp16 convert + weight convert --------------------
__global__ void k_gate_cvt(const float* __restrict__ x, const float* __restrict__ Wg,
                           const float* __restrict__ bg,
                           const float* __restrict__ W1, const float* __restrict__ W2,
                           __half* __restrict__ o1, __half* __restrict__ o2, int n4) {
    int tid = threadIdx.x;
    if (blockIdx.x >= N_TOKENS) {
        int cb = blockIdx.x - N_TOKENS;
        for (int i = cb * 128 + tid; i < 2 * n4; i += NCVT_BLOCKS * 128) {
            const float* W; __half* o; int j = i;
            if (j < n4) { W = W1; o = o1; } else { W = W2; o = o2; j -= n4; }
            float4 v = ((const float4*)W)[j];
            __half2 a = {__float2half_rn(v.x), __float2half_rn(v.y)};
            __half2 b = {__float2half_rn(v.z), __float2half_rn(v.w)};
            ((uint2*)o)[j] = make_uint2(*(uint32_t*)&a, *(uint32_t*)&b);
        }
        return;
    }
    int t = blockIdx.x;
    float acc[NEXP];
#pragma unroll
    for (int e = 0; e < NEXP; e++) acc[e] = 0.0f;
    const float* xr = x + (size_t)t * HIDDEN;
    size_t xo = (size_t)t * HIDDEN;
    for (int k = tid; k < HIDDEN; k += 128) {
        float xv = xr[k];
        g_xc[xo + k] = __float2half_rn(xv);
        const float* wr = Wg + k * NEXP;
#pragma unroll
        for (int e = 0; e < NEXP; e++) acc[e] += xv * wr[e];
    }
    __shared__ float s[128 * NEXP];
#pragma unroll
    for (int e = 0; e < NEXP; e++) s[tid * NEXP + e] = acc[e];
    __syncthreads();
    if (tid < NEXP) {
        float sum = 0.0f;
        for (int r = 0; r < 128; r++) sum += s[r * NEXP + tid];
        s[tid] = sum + bg[tid];
    }
    __syncthreads();
    if (tid == 0) {
        float best = -INFINITY; int e0 = 0;
#pragma unroll
        for (int e = 0; e < NEXP; e++) if (s[e] > best) { best = s[e]; e0 = e; }
        float best2 = -INFINITY; int e1 = 0;
#pragma unroll
        for (int e = 0; e < NEXP; e++) if (e != e0 && s[e] > best2) { best2 = s[e]; e1 = e; }
        float w1 = expf(best2 - best);
        float inv = 1.0f / (1.0f + w1);
        g_token_e[t * 2 + 0] = e0;  g_token_e[t * 2 + 1] = e1;
        g_token_w[t * 2 + 0] = inv; g_token_w[t * 2 + 1] = w1 * inv;
        atomicAdd(&g_count[e0], 1);
        atomicAdd(&g_count[e1], 1);
    }
}

// ---------------- scan: padded offsets + tile map ----------------------------------
__global__ void k_scan() {
    if (threadIdx.x != 0) return;
    int off = 0, nt = 0;
    for (int e = 0; e < NEXP; e++) {
        g_off_pad[e] = off;
        int mt = (g_count[e] + 127) >> 7;
        for (int i = 0; i < mt; i++) { g_tile_e[nt] = e; g_tile_base[nt] = off + i * 128; nt++; }
        off += mt * 128;
    }
    g_ntiles = nt; g_npad = off;
}

// ---------------- scatter ----------------------------------------------------------
__global__ void k_scatter() {
    int t = blockIdx.x * blockDim.x + threadIdx.x;
    if (t >= N_TOKENS) return;
#pragma unroll
    for (int k = 0; k < 2; k++) {
        int e    = g_token_e[t * 2 + k];
        int pos  = atomicAdd(&g_cursor[e], 1);
        int slot = g_off_pad[e] + pos;
        g_tok[slot]    = t;
        g_slot_w[slot] = g_token_w[t * 2 + k];
    }
}

// ---------------- combined one-shot MoE GEMM (GEMM1 then GEMM2, single launch) ------
// bids [0, NW1): GEMM1 tiles (mtile = bid>>5, n0 = (bid&31)*128).
// bids [NW1, NWALL): GEMM2 tiles (mtile = v>>3, n0 = (v&7)*128), spin until
// g_done[mtile]==32. Dispatch order (bid-increasing) guarantees no deadlock and
// overlaps GEMM1's tail with GEMM2's head. Tile body = R12 config: 128x128 tile,
// 512 thr (16 warps, warp 32x32), BK=32, 4-stage cp.async, 2 CTAs/SM.
// smem: [0,512) bias; stages at 1024 + s*18944: A [128][40]h | B [32][136]h
#define STAGE_B   18944u
#define OFF_B     10240u
#define NSTG      4
#define SMEM_GEMM (1024u + 4u * STAGE_B)

template <int KD, int ND, bool IS1>
__device__ __forceinline__ void tile_work(uint32_t sb, float* bs, int e, int base,
                                          int n0, const float* __restrict__ bias,
                                          float* __restrict__ out) {
    int tid  = threadIdx.x;
    int wid  = tid >> 5, lane = tid & 31;
    int wm   = wid & 3, wn = wid >> 2;

    int la_row = (lane & 15);
    int la_k8  = (lane >> 4) * 8;
    int lb_k   = (lane & 15);
    int lb_n8  = (lane >> 4) * 8;
    int ar = tid >> 2, aj = tid & 3;
    int br = tid >> 4, bj = tid & 15;

    const __half* B = (IS1 ? g_W1h : g_W2h) + (size_t)e * KD * ND;
    if (tid < 128) bs[tid] = bias[(size_t)e * ND + n0 + tid];

    const __half* arow;
    if (IS1) arow = g_xc + (size_t)g_tok[base + ar] * KD;
    else     arow = g_hh + (size_t)(base + ar) * KD;

    auto load_stage = [&](int st, int kb) {
        uint32_t s0 = sb + 1024u + (uint32_t)st * STAGE_B;
        int k0 = kb * 32;
        cpa16(s0 + (uint32_t)ar * 80u + (uint32_t)aj * 16u, arow + k0 + aj * 8);
        const __half* gb = B + (size_t)(k0 + br) * ND + n0;
        cpa16(s0 + OFF_B + (uint32_t)br * 272u + (uint32_t)bj * 16u, gb + bj * 8);
        asm volatile("cp.async.commit_group;");
    };

    float acc[2][4][4];
#pragma unroll
    for (int i = 0; i < 2; i++)
#pragma unroll
        for (int j = 0; j < 4; j++)
#pragma unroll
            for (int q = 0; q < 4; q++) acc[i][j][q] = 0.0f;

    constexpr int NKB = KD / 32;
    load_stage(0, 0);
    load_stage(1, 1);
    load_stage(2, 2);

    for (int kb = 0; kb < NKB; kb++) {
        int rem = NKB - 1 - kb;
        if (rem >= 2)      asm volatile("cp.async.wait_group 2;");
        else if (rem == 1) asm volatile("cp.async.wait_group 1;");
        else               asm volatile("cp.async.wait_group 0;");
        __syncthreads();
        if (kb + 3 < NKB) load_stage((kb + 3) & (NSTG - 1), kb + 3);

        uint32_t s0 = sb + 1024u + (uint32_t)(kb & (NSTG - 1)) * STAGE_B;
#pragma unroll
        for (int kk = 0; kk < 32; kk += 16) {
            uint32_t ah[2][4], b[2][4];
#pragma unroll
            for (int mi = 0; mi < 2; mi++) {
                uint32_t a = s0 + (uint32_t)(wm * 32 + mi * 16 + la_row) * 80u
                           + (uint32_t)(kk + la_k8) * 2u;
                ldm_x4(ah[mi], a);
            }
#pragma unroll
            for (int g = 0; g < 2; g++) {
                uint32_t bb = s0 + OFF_B + (uint32_t)(kk + lb_k) * 272u
                            + (uint32_t)(wn * 32 + g * 16 + lb_n8) * 2u;
                ldm_x4t(b[g], bb);
            }
#pragma unroll
            for (int mi = 0; mi < 2; mi++)
#pragma unroll
                for (int g = 0; g < 2; g++) {
                    mma_f16(acc[mi][2 * g],     ah[mi], b[g][0], b[g][1]);
                    mma_f16(acc[mi][2 * g + 1], ah[mi], b[g][2], b[g][3]);
                }
        }
    }
    __syncthreads();

    // epilogue
    int rbase = wm * 32 + (lane >> 2);
    int cbase = wn * 32 + (lane & 3) * 2;
#pragma unroll
    for (int mi = 0; mi < 2; mi++) {
        int s0r = base + rbase + mi * 16;
        int s1r = s0r + 8;
        if (IS1) {
#pragma unroll
            for (int nf = 0; nf < 4; nf++) {
                int c = cbase + nf * 8;
                float b0 = bs[c], b1v = bs[c + 1];
                float v0 = fmaxf(acc[mi][nf][0] + b0,  0.0f);
                float v1 = fmaxf(acc[mi][nf][1] + b1v, 0.0f);
                float v2 = fmaxf(acc[mi][nf][2] + b0,  0.0f);
                float v3 = fmaxf(acc[mi][nf][3] + b1v, 0.0f);
                __half2 p0 = {__float2half_rn(v0), __float2half_rn(v1)};
                __half2 p1 = {__float2half_rn(v2), __float2half_rn(v3)};
                *(__half2*)(g_hh + (size_t)s0r * FFN + n0 + c) = p0;
                *(__half2*)(g_hh + (size_t)s1r * FFN + n0 + c) = p1;
            }
        } else {
            int   t0 = g_tok[s0r],    t1 = g_tok[s1r];
            float w0 = g_slot_w[s0r], w1 = g_slot_w[s1r];
            float* o0 = out + (size_t)t0 * HIDDEN + n0;
            float* o1 = out + (size_t)t1 * HIDDEN + n0;
#pragma unroll
            for (int nf = 0; nf < 4; nf++) {
                int c = cbase + nf * 8;
                float b0 = bs[c], b1v = bs[c + 1];
                atomicAdd(o0 + c,     w0 * (acc[mi][nf][0] + b0));
                atomicAdd(o0 + c + 1, w0 * (acc[mi][nf][1] + b1v));
                atomicAdd(o1 + c,     w1 * (acc[mi][nf][2] + b0));
                atomicAdd(o1 + c + 1, w1 * (acc[mi][nf][3] + b1v));
            }
        }
    }
}

__global__ void __launch_bounds__(512, 2) k_moe(const float* __restrict__ b1,
                                                const float* __restrict__ b2,
                                                float* __restrict__ out) {
    extern __shared__ char smem[];
    uint32_t sb = smem_u32(smem);
    float* bs  = (float*)smem;
    int tid = threadIdx.x;
    int w   = blockIdx.x;
    int nt  = g_ntiles;

    if (w < NW1) {
        int mtile = w >> 5;
        if (mtile >= nt) return;
        int n0 = (w & 31) * 128;
        tile_work<HIDDEN, FFN, true>(sb, bs, g_tile_e[mtile], g_tile_base[mtile],
                                     n0, b1, out);
        __threadfence();                          // release h rows
        __syncthreads();
        if (tid == 0) atomicAdd(&g_done[mtile], 1);
    } else {
        int v     = w - NW1;
        int mtile = v >> 3;
        if (mtile >= nt) return;
        int n0 = (v & 7) * 128;
        if (tid == 0) {
            volatile int* p = &g_done[mtile];
            while (*p < 32) __nanosleep(100);
        }
        __syncthreads();
        __threadfence();                          // acquire: h rows visible
        tile_work<FFN, HIDDEN, false>(sb, bs, g_tile_e[mtile], g_tile_base[mtile],
                                      n0, b2, out);
    }
}

// ---------------- launch -----------------------------------------------------------
extern "C" void kernel_launch(void* const* d_in, const int* in_sizes, int n_in,
                              void* d_out, int out_size) {
    const float* x  = (const float*)d_in[0];
    const float* Wg = (const float*)d_in[1];
    const float* bg = (const float*)d_in[2];
    const float* W1 = (const float*)d_in[3];
    const float* b1 = (const float*)d_in[4];
    const float* W2 = (const float*)d_in[5];
    const float* b2 = (const float*)d_in[6];
    float* out = (float*)d_out;

    __half *w1h, *w2h;
    cudaGetSymbolAddress((void**)&w1h, g_W1h);
    cudaGetSymbolAddress((void**)&w2h, g_W2h);
    void *cnt, *cur, *tok, *sw, *don;
    cudaGetSymbolAddress(&cnt, g_count);
    cudaGetSymbolAddress(&cur, g_cursor);
    cudaGetSymbolAddress(&tok, g_tok);
    cudaGetSymbolAddress(&sw,  g_slot_w);
    cudaGetSymbolAddress(&don, g_done);

    cudaFuncSetAttribute((const void*)k_moe,
                         cudaFuncAttributeMaxDynamicSharedMemorySize, SMEM_GEMM);

    cudaMemsetAsync(out, 0, (size_t)out_size * sizeof(float));
    cudaMemsetAsync(cnt, 0, NEXP * sizeof(int));
    cudaMemsetAsync(cur, 0, NEXP * sizeof(int));
    cudaMemsetAsync(tok, 0, NSLOTS_PAD * sizeof(int));
    cudaMemsetAsync(sw,  0, NSLOTS_PAD * sizeof(float));
    cudaMemsetAsync(don, 0, MAXTILES * sizeof(int));

    int n4 = NEXP * HIDDEN * FFN / 4;
    k_gate_cvt<<<N_TOKENS + NCVT_BLOCKS, 128>>>(x, Wg, bg, W1, W2, w1h, w2h, n4);
    k_scan<<<1, 32>>>();
    k_scatter<<<(N_TOKENS + 255) / 256, 256>>>();

    // combined one-shot GEMM1+GEMM2 (bid-ordered dependency overlap)
    k_moe<<<NWALL, 512, SMEM_GEMM>>>(b1, b2, out);
}

// round 17
// speedup vs baseline: 1.5705x; 1.5705x over previous
#include <cuda_runtime.h>
#include <cuda_fp16.h>
#include <math.h>
#include <stdint.h>

#define N_TOKENS 16384
#define HIDDEN   1024
#define FFN      4096
#define NEXP     8
#define NSLOTS   (N_TOKENS * 2)
#define NSLOTS_PAD (NSLOTS + NEXP * 128)   // 33792
#define MAXTILES 272
#define NCVT_BLOCKS 2048                    // gate_cvt converts only W1 now
#define CVT2_ROWS 8                         // extra y-rows on GEMM1 grid for W2 cvt

// ---------------- scratch (device globals) -----------------------------------------
__device__ __half g_W1h[(size_t)NEXP * HIDDEN * FFN];   // [e][K][N] fp16
__device__ __half g_W2h[(size_t)NEXP * FFN * HIDDEN];
__device__ __half g_xc[(size_t)N_TOKENS * HIDDEN];      // x as fp16 (per token)
__device__ __half g_hh[(size_t)NSLOTS_PAD * FFN];       // h fp16
__device__ int   g_tok[NSLOTS_PAD];                     // slot -> token (pad: 0)
__device__ float g_slot_w[NSLOTS_PAD];                  // slot -> combine weight (pad: 0)
__device__ int   g_token_e[NSLOTS];
__device__ float g_token_w[NSLOTS];
__device__ int   g_count[NEXP], g_cursor[NEXP], g_off_pad[NEXP];
__device__ int   g_tile_e[MAXTILES], g_tile_base[MAXTILES];
__device__ int   g_ntiles, g_npad;

// ---------------- helpers ----------------------------------------------------------
__device__ __forceinline__ uint32_t smem_u32(const void* p) {
    uint32_t a;
    asm("{ .reg .u64 t; cvta.to.shared.u64 t, %1; cvt.u32.u64 %0, t; }" : "=r"(a) : "l"(p));
    return a;
}
__device__ __forceinline__ void cpa16(uint32_t d, const void* s) {
    asm volatile("cp.async.cg.shared.global [%0], [%1], 16;" :: "r"(d), "l"(s));
}
__device__ __forceinline__ void ldm_x4(uint32_t* r, uint32_t a) {
    asm volatile("ldmatrix.sync.aligned.m8n8.x4.shared.b16 {%0,%1,%2,%3}, [%4];"
                 : "=r"(r[0]), "=r"(r[1]), "=r"(r[2]), "=r"(r[3]) : "r"(a));
}
__device__ __forceinline__ void ldm_x4t(uint32_t* r, uint32_t a) {
    asm volatile("ldmatrix.sync.aligned.m8n8.x4.trans.shared.b16 {%0,%1,%2,%3}, [%4];"
                 : "=r"(r[0]), "=r"(r[1]), "=r"(r[2]), "=r"(r[3]) : "r"(a));
}
__device__ __forceinline__ void mma_f16(float* d, const uint32_t* a, uint32_t b0, uint32_t b1) {
    asm volatile(
        "mma.sync.aligned.m16n8k16.row.col.f32.f16.f16.f32 "
        "{%0,%1,%2,%3}, {%4,%5,%6,%7}, {%8,%9}, {%0,%1,%2,%3};"
        : "+f"(d[0]), "+f"(d[1]), "+f"(d[2]), "+f"(d[3])
        : "r"(a[0]), "r"(a[1]), "r"(a[2]), "r"(a[3]), "r"(b0), "r"(b1));
}
__device__ __forceinline__ void cvt_chunk(const float* __restrict__ W,
                                          __half* __restrict__ o, int i) {
    float4 v = ((const float4*)W)[i];
    __half2 a = {__float2half_rn(v.x), __float2half_rn(v.y)};
    __half2 b = {__float2half_rn(v.z), __float2half_rn(v.w)};
    ((uint2*)o)[i] = make_uint2(*(uint32_t*)&a, *(uint32_t*)&b);
}

// ---------------- fused gating + x fp16 convert + W1 convert ------------------------
__global__ void k_gate_cvt(const float* __restrict__ x, const float* __restrict__ Wg,
                           const float* __restrict__ bg,
                           const float* __restrict__ W1,
                           __half* __restrict__ o1, int n4) {
    int tid = threadIdx.x;
    if (blockIdx.x >= N_TOKENS) {
        int cb = blockIdx.x - N_TOKENS;
        for (int i = cb * 128 + tid; i < n4; i += NCVT_BLOCKS * 128)
            cvt_chunk(W1, o1, i);
        return;
    }
    int t = blockIdx.x;
    float acc[NEXP];
#pragma unroll
    for (int e = 0; e < NEXP; e++) acc[e] = 0.0f;
    const float* xr = x + (size_t)t * HIDDEN;
    size_t xo = (size_t)t * HIDDEN;
    for (int k = tid; k < HIDDEN; k += 128) {
        float xv = xr[k];
        g_xc[xo + k] = __float2half_rn(xv);
        const float* wr = Wg + k * NEXP;
#pragma unroll
        for (int e = 0; e < NEXP; e++) acc[e] += xv * wr[e];
    }
    __shared__ float s[128 * NEXP];
#pragma unroll
    for (int e = 0; e < NEXP; e++) s[tid * NEXP + e] = acc[e];
    __syncthreads();
    if (tid < NEXP) {
        float sum = 0.0f;
        for (int r = 0; r < 128; r++) sum += s[r * NEXP + tid];
        s[tid] = sum + bg[tid];
    }
    __syncthreads();
    if (tid == 0) {
        float best = -INFINITY; int e0 = 0;
#pragma unroll
        for (int e = 0; e < NEXP; e++) if (s[e] > best) { best = s[e]; e0 = e; }
        float best2 = -INFINITY; int e1 = 0;
#pragma unroll
        for (int e = 0; e < NEXP; e++) if (e != e0 && s[e] > best2) { best2 = s[e]; e1 = e; }
        float w1 = expf(best2 - best);
        float inv = 1.0f / (1.0f + w1);
        g_token_e[t * 2 + 0] = e0;  g_token_e[t * 2 + 1] = e1;
        g_token_w[t * 2 + 0] = inv; g_token_w[t * 2 + 1] = w1 * inv;
        atomicAdd(&g_count[e0], 1);
        atomicAdd(&g_count[e1], 1);
    }
}

// ---------------- scan: padded offsets + tile map ----------------------------------
__global__ void k_scan() {
    if (threadIdx.x != 0) return;
    int off = 0, nt = 0;
    for (int e = 0; e < NEXP; e++) {
        g_off_pad[e] = off;
        int mt = (g_count[e] + 127) >> 7;
        for (int i = 0; i < mt; i++) { g_tile_e[nt] = e; g_tile_base[nt] = off + i * 128; nt++; }
        off += mt * 128;
    }
    g_ntiles = nt; g_npad = off;
}

// ---------------- scatter ----------------------------------------------------------
__global__ void k_scatter() {
    int t = blockIdx.x * blockDim.x + threadIdx.x;
    if (t >= N_TOKENS) return;
#pragma unroll
    for (int k = 0; k < 2; k++) {
        int e    = g_token_e[t * 2 + k];
        int pos  = atomicAdd(&g_cursor[e], 1);
        int slot = g_off_pad[e] + pos;
        g_tok[slot]    = t;
        g_slot_w[slot] = g_token_w[t * 2 + k];
    }
}

// ---------------- mma.sync fp16 GEMM (R12 config) -----------------------------------
// block: 512 thr (16 warps, 4m x 4n), tile 128x128, warp tile 32x32, BK=32,
// 4-stage cp.async, 2 CTAs/SM.
// GEMM1 additionally carries CVT2_ROWS extra grid-y rows (highest bids -> run in
// GEMM1's tail wave) that convert W2 fp32->fp16 for GEMM2.
// smem: [0,512) bias; stages at 1024 + s*18944: A [128][40]h | B [32][136]h
// GEMM1 epilogue -> g_hh (fp16, relu); GEMM2 epilogue -> weighted atomicAdd into out.
#define STAGE_B   18944u
#define OFF_B     10240u
#define NSTG      4
#define SMEM_GEMM (1024u + 4u * STAGE_B)

template <int KDIM, int NDIM, bool IS_FFN>
__global__ void __launch_bounds__(512, 2) k_gemm(const float* __restrict__ bias,
                                                 float* __restrict__ out,
                                                 const float* __restrict__ Wcvt,
                                                 __half* __restrict__ ocvt, int ncvt4) {
    if (IS_FFN && blockIdx.y >= MAXTILES) {
        // W2 converter blocks: fill GEMM1's tail wave with DRAM-bound work
        int cb  = (blockIdx.y - MAXTILES) * gridDim.x + blockIdx.x;
        int tid = threadIdx.x;
        for (int i = cb * 512 + tid; i < ncvt4; i += CVT2_ROWS * 32 * 512)
            cvt_chunk(Wcvt, ocvt, i);
        return;
    }
    int tile = blockIdx.y;
    if (tile >= g_ntiles) return;
    int e    = g_tile_e[tile];
    int base = g_tile_base[tile];
    int n0   = blockIdx.x * 128;

    extern __shared__ char smem[];
    uint32_t sb = smem_u32(smem);
    float* bs = (float*)smem;

    int tid  = threadIdx.x;
    int wid  = tid >> 5, lane = tid & 31;
    int wm   = wid & 3, wn = wid >> 2;           // warp tile: rows wm*32, cols wn*32

    const __half* B = (IS_FFN ? g_W1h : g_W2h) + (size_t)e * KDIM * NDIM;

    if (tid < 128) bs[tid] = bias[(size_t)e * NDIM + n0 + tid];

    // load maps (512 threads, BK=32): 1 chunk (16B) per thread per operand
    int ar = tid >> 2;                   // A: 128 rows
    int aj = tid & 3;                    // 4 chunks/row
    int br = tid >> 4;                   // B: 32 k-rows
    int bj = tid & 15;                   // 16 chunks/row

    const __half* arow;
    if (IS_FFN) arow = g_xc + (size_t)g_tok[base + ar] * KDIM;
    else        arow = g_hh + (size_t)(base + ar) * KDIM;

    auto load_stage = [&](int st, int kb) {
        uint32_t s0 = sb + 1024u + (uint32_t)st * STAGE_B;
        int k0 = kb * 32;
        cpa16(s0 + (uint32_t)ar * 80u + (uint32_t)aj * 16u, arow + k0 + aj * 8);
        const __half* gb = B + (size_t)(k0 + br) * NDIM + n0;
        cpa16(s0 + OFF_B + (uint32_t)br * 272u + (uint32_t)bj * 16u, gb + bj * 8);
        asm volatile("cp.async.commit_group;");
    };

    float acc[2][4][4];
#pragma unroll
    for (int i = 0; i < 2; i++)
#pragma unroll
        for (int j = 0; j < 4; j++)
#pragma unroll
            for (int q = 0; q < 4; q++) acc[i][j][q] = 0.0f;

    constexpr int NKB = KDIM / 32;
    load_stage(0, 0);
    load_stage(1, 1);
    load_stage(2, 2);

    int la_row = (lane & 15);
    int la_k8  = (lane >> 4) * 8;
    int lb_k   = (lane & 15);
    int lb_n8  = (lane >> 4) * 8;

    for (int kb = 0; kb < NKB; kb++) {
        int rem = NKB - 1 - kb;
        if (rem >= 2)      asm volatile("cp.async.wait_group 2;");
        else if (rem == 1) asm volatile("cp.async.wait_group 1;");
        else               asm volatile("cp.async.wait_group 0;");
        __syncthreads();
        if (kb + 3 < NKB) load_stage((kb + 3) & (NSTG - 1), kb + 3);

        uint32_t s0 = sb + 1024u + (uint32_t)(kb & (NSTG - 1)) * STAGE_B;
#pragma unroll
        for (int kk = 0; kk < 32; kk += 16) {
            uint32_t ah[2][4], b[2][4];
#pragma unroll
            for (int mi = 0; mi < 2; mi++) {
                uint32_t a = s0 + (uint32_t)(wm * 32 + mi * 16 + la_row) * 80u
                           + (uint32_t)(kk + la_k8) * 2u;
                ldm_x4(ah[mi], a);
            }
#pragma unroll
            for (int g = 0; g < 2; g++) {
                uint32_t bb = s0 + OFF_B + (uint32_t)(kk + lb_k) * 272u
                            + (uint32_t)(wn * 32 + g * 16 + lb_n8) * 2u;
                ldm_x4t(b[g], bb);
            }
#pragma unroll
            for (int mi = 0; mi < 2; mi++)
#pragma unroll
                for (int g = 0; g < 2; g++) {
                    mma_f16(acc[mi][2 * g],     ah[mi], b[g][0], b[g][1]);
                    mma_f16(acc[mi][2 * g + 1], ah[mi], b[g][2], b[g][3]);
                }
        }
    }
    __syncthreads();

    // epilogue
    {
        int rbase = wm * 32 + (lane >> 2);
        int cbase = wn * 32 + (lane & 3) * 2;
#pragma unroll
        for (int mi = 0; mi < 2; mi++) {
            int s0r = base + rbase + mi * 16;     // slot of first row
            int s1r = s0r + 8;                    // slot of second row
            if (IS_FFN) {
#pragma unroll
                for (int nf = 0; nf < 4; nf++) {
                    int c = cbase + nf * 8;
                    float b0 = bs[c], b1 = bs[c + 1];
                    float v0 = fmaxf(acc[mi][nf][0] + b0, 0.0f);
                    float v1 = fmaxf(acc[mi][nf][1] + b1, 0.0f);
                    float v2 = fmaxf(acc[mi][nf][2] + b0, 0.0f);
                    float v3 = fmaxf(acc[mi][nf][3] + b1, 0.0f);
                    __half2 p0 = {__float2half_rn(v0), __float2half_rn(v1)};
                    __half2 p1 = {__float2half_rn(v2), __float2half_rn(v3)};
                    *(__half2*)(g_hh + (size_t)s0r * FFN + n0 + c) = p0;
                    *(__half2*)(g_hh + (size_t)s1r * FFN + n0 + c) = p1;
                }
            } else {
                int   t0 = g_tok[s0r],    t1 = g_tok[s1r];
                float w0 = g_slot_w[s0r], w1 = g_slot_w[s1r];
                float* o0 = out + (size_t)t0 * HIDDEN + n0;
                float* o1 = out + (size_t)t1 * HIDDEN + n0;
#pragma unroll
                for (int nf = 0; nf < 4; nf++) {
                    int c = cbase + nf * 8;
                    float b0 = bs[c], b1 = bs[c + 1];
                    atomicAdd(o0 + c,     w0 * (acc[mi][nf][0] + b0));
                    atomicAdd(o0 + c + 1, w0 * (acc[mi][nf][1] + b1));
                    atomicAdd(o1 + c,     w1 * (acc[mi][nf][2] + b0));
                    atomicAdd(o1 + c + 1, w1 * (acc[mi][nf][3] + b1));
                }
            }
        }
    }
}

// ---------------- launch -----------------------------------------------------------
extern "C" void kernel_launch(void* const* d_in, const int* in_sizes, int n_in,
                              void* d_out, int out_size) {
    const float* x  = (const float*)d_in[0];
    const float* Wg = (const float*)d_in[1];
    const float* bg = (const float*)d_in[2];
    const float* W1 = (const float*)d_in[3];
    const float* b1 = (const float*)d_in[4];
    const float* W2 = (const float*)d_in[5];
    const float* b2 = (const float*)d_in[6];
    float* out = (float*)d_out;

    __half *w1h, *w2h;
    cudaGetSymbolAddress((void**)&w1h, g_W1h);
    cudaGetSymbolAddress((void**)&w2h, g_W2h);
    void *cnt, *cur, *tok, *sw;
    cudaGetSymbolAddress(&cnt, g_count);
    cudaGetSymbolAddress(&cur, g_cursor);
    cudaGetSymbolAddress(&tok, g_tok);
    cudaGetSymbolAddress(&sw,  g_slot_w);

    cudaFuncSetAttribute((const void*)k_gemm<HIDDEN, FFN, true>,
                         cudaFuncAttributeMaxDynamicSharedMemorySize, SMEM_GEMM);
    cudaFuncSetAttribute((const void*)k_gemm<FFN, HIDDEN, false>,
                         cudaFuncAttributeMaxDynamicSharedMemorySize, SMEM_GEMM);

    cudaMemsetAsync(out, 0, (size_t)out_size * sizeof(float));
    cudaMemsetAsync(cnt, 0, NEXP * sizeof(int));
    cudaMemsetAsync(cur, 0, NEXP * sizeof(int));
    cudaMemsetAsync(tok, 0, NSLOTS_PAD * sizeof(int));
    cudaMemsetAsync(sw,  0, NSLOTS_PAD * sizeof(float));

    int n4 = NEXP * HIDDEN * FFN / 4;
    k_gate_cvt<<<N_TOKENS + NCVT_BLOCKS, 128>>>(x, Wg, bg, W1, w1h, n4);
    k_scan<<<1, 32>>>();
    k_scatter<<<(N_TOKENS + 255) / 256, 256>>>();

    // pass 1: h = relu(gather(xc) @ W1[e] + b1[e]); tail rows convert W2 -> fp16
    k_gemm<HIDDEN, FFN, true>
        <<<dim3(FFN / 128, MAXTILES + CVT2_ROWS), 512, SMEM_GEMM>>>(
            b1, out, W2, w2h, n4);
    // pass 2: out += w * (h @ W2[e] + b2[e])   (fused combine, atomic)
    k_gemm<FFN, HIDDEN, false>
        <<<dim3(HIDDEN / 128, MAXTILES), 512, SMEM_GEMM>>>(
            b2, out, (const float*)nullptr, ((__half*)nullptr), 0);
}